// round 7
// baseline (speedup 1.0000x reference)
#include <cuda_runtime.h>
#include <cuda_bf16.h>

// CALayer SE, single-pass persistent pipelined kernel, 2 batches/round.
// 1024 co-resident blocks (launch_bounds(256,7): 7x148=1036 slots), each owns
// a quarter-plane (16KB) per batch. 8 rounds of 2 batches:
//   round r: read+sum batches {2r,2r+1} (fills L2), publish counter;
//            then gate+scale round r-1 (counter wait hidden by in-flight reads,
//            re-read from L2, st.cs out).
// Traffic: x read once + out written once = 537MB DRAM.

#define BATCH 16
#define CHAN 256
#define CR 16
#define HW 16384               // floats per plane
#define PLANE_F4 (HW/4)        // 4096
#define QF4 (PLANE_F4/4)       // 1024 float4 per quarter chunk
#define NBLK 1024
#define TPB 256
#define BPR 2
#define NROUNDS (BATCH/BPR)    // 8

__device__ float g_part[BATCH * CHAN * 4];
__device__ int   g_cnt[NROUNDS];

__global__ void init_kernel() {
    if (threadIdx.x < NROUNDS) g_cnt[threadIdx.x] = 0;
}

__device__ __forceinline__ void stcs4(float4* p, float4 v) {
    asm volatile("st.global.cs.v4.f32 [%0], {%1,%2,%3,%4};"
                 :: "l"(p), "f"(v.x), "f"(v.y), "f"(v.z), "f"(v.w) : "memory");
}

__global__ __launch_bounds__(TPB, 7) void fused_se_kernel(
    const float* __restrict__ x, float* __restrict__ out,
    const float* __restrict__ w1, const float* __restrict__ b1,
    const float* __restrict__ w2, const float* __restrict__ b2)
{
    __shared__ float sred[BPR][8];
    __shared__ float smean[BPR][CHAN];
    __shared__ float shid[BPR][CR];
    __shared__ float sscale[BPR];

    const int chan    = blockIdx.x >> 2;   // 0..255
    const int quarter = blockIdx.x & 3;    // 0..3
    const int tid  = threadIdx.x;
    const int lane = tid & 31;
    const int wid  = tid >> 5;
    const size_t qoff = (size_t)quarter * QF4;

    const float4* __restrict__ x4 = reinterpret_cast<const float4*>(x);
    float4* __restrict__ o4 = reinterpret_cast<float4*>(out);

    auto read_sum = [&](int r) {
        #pragma unroll
        for (int s = 0; s < BPR; s++) {
            const int p = ((r * BPR + s) << 8) | chan;
            const float4* __restrict__ xp = x4 + (size_t)p * PLANE_F4 + qoff;
            float acc = 0.f;
            #pragma unroll
            for (int i = 0; i < 4; i++) {
                float4 v = xp[tid + i * TPB];      // .ca -> L2 resident
                acc += (v.x + v.y) + (v.z + v.w);
            }
            #pragma unroll
            for (int o = 16; o; o >>= 1) acc += __shfl_xor_sync(0xFFFFFFFF, acc, o);
            if (lane == 0) sred[s][wid] = acc;
        }
        __syncthreads();
        if (tid == 0) {
            #pragma unroll
            for (int s = 0; s < BPR; s++) {
                float t = 0.f;
                #pragma unroll
                for (int w = 0; w < 8; w++) t += sred[s][w];
                const int p = ((r * BPR + s) << 8) | chan;
                g_part[p * 4 + quarter] = t;
            }
            __threadfence();
            atomicAdd(&g_cnt[r], 1);
        }
        __syncthreads();
    };

    auto gate_scale = [&](int r) {
        const int b0 = r * BPR;
        if (tid == 0) {
            while (atomicAdd(&g_cnt[r], 0) < NBLK) __nanosleep(64);
            __threadfence();
        }
        __syncthreads();
        // means for both batches (tid == channel)
        #pragma unroll
        for (int s = 0; s < BPR; s++) {
            const int q = (((b0 + s) << 8) + tid) * 4;
            smean[s][tid] = (__ldcg(&g_part[q]) + __ldcg(&g_part[q + 1]) +
                             __ldcg(&g_part[q + 2]) + __ldcg(&g_part[q + 3])) * (1.0f / HW);
        }
        __syncthreads();
        // hidden: 32 rows (2 batches x 16) over 8 warps, 4 rows each
        #pragma unroll
        for (int j = 0; j < 4; j++) {
            const int row = wid * 4 + j;
            const int s = row >> 4;
            const int rr = row & 15;
            float acc = 0.f;
            #pragma unroll
            for (int c = lane; c < CHAN; c += 32)
                acc += __ldg(&w1[rr * CHAN + c]) * smean[s][c];
            #pragma unroll
            for (int o = 16; o; o >>= 1) acc += __shfl_xor_sync(0xFFFFFFFF, acc, o);
            if (lane == 0) shid[s][rr] = fmaxf(acc + __ldg(&b1[rr]), 0.f);
        }
        __syncthreads();
        if (tid < BPR) {
            float acc = __ldg(&b2[chan]);
            #pragma unroll
            for (int rr = 0; rr < CR; rr++)
                acc += __ldg(&w2[chan * CR + rr]) * shid[tid][rr];
            sscale[tid] = 1.0f / (1.0f + __expf(-acc));
        }
        __syncthreads();
        // re-read from L2, scale, stream out
        #pragma unroll
        for (int s = 0; s < BPR; s++) {
            const int p = ((b0 + s) << 8) | chan;
            const float sc = sscale[s];
            const float4* __restrict__ xp = x4 + (size_t)p * PLANE_F4 + qoff;
            float4* __restrict__ op = o4 + (size_t)p * PLANE_F4 + qoff;
            #pragma unroll
            for (int i = 0; i < 4; i++) {
                float4 v = xp[tid + i * TPB];      // L2 hit
                v.x *= sc; v.y *= sc; v.z *= sc; v.w *= sc;
                stcs4(&op[tid + i * TPB], v);
            }
        }
        __syncthreads();
    };

    // ---------- pipelined main loop ----------
    read_sum(0);
    for (int r = 1; r < NROUNDS; r++) {
        read_sum(r);
        gate_scale(r - 1);
    }
    gate_scale(NROUNDS - 1);
}

extern "C" void kernel_launch(void* const* d_in, const int* in_sizes, int n_in,
                              void* d_out, int out_size) {
    const float* x  = (const float*)d_in[0];
    const float* w1 = (const float*)d_in[1];
    const float* b1 = (const float*)d_in[2];
    const float* w2 = (const float*)d_in[3];
    const float* b2 = (const float*)d_in[4];
    float* out = (float*)d_out;

    init_kernel<<<1, 32>>>();
    fused_se_kernel<<<NBLK, TPB>>>(x, out, w1, b1, w2, b2);
}